// round 8
// baseline (speedup 1.0000x reference)
#include <cuda_runtime.h>
#include <cuda_bf16.h>
#include <cstdint>

static constexpr int NB = 16, NN = 2048, DD = 64;
static constexpr int BM = 64, BN = 128, NKT = NN / BN, TB = 256;

// Pre-converted bf16 hi/lo panels, SW128-swizzled, tile-blocked (128-row blocks):
// g_conv[(t*16 + b)*16 + blk] -> 32KB {hi 16KB, lo 16KB}, t: 0=Q,1=K,2=V
__device__ __align__(128) uint8_t g_conv[(size_t)3 * 16 * 16 * 32768];

// SMEM (112KB/CTA -> 2 CTAs/SM):
//   QH 8K @0, QL 8K @8192 (64 rows x 128B each)
//   ST0=16384, 96KB stage region:
//     pass1: Kh stage s @ ST0 + s*16384
//     pass2: Kst (Kh+Kl 32KB) @ ST0; V stage s @ ST0+32768+s*32768 {Vh,Vl}
//   row-sum scratch @ ST0+65536 (dead between passes)
//   final O-reduce scratch @ ST0 (dead after loop)
static constexpr int SM_QH = 0, SM_QL = 8192;
static constexpr int ST0 = 16384;
static constexpr int SMEM_TOTAL = ST0 + 98304;   // 114688 = 112KB

__device__ __forceinline__ uint32_t smem_u32(const void* p) {
    uint32_t a;
    asm("{ .reg .u64 t; cvta.to.shared.u64 t, %1; cvt.u32.u64 %0, t; }" : "=r"(a) : "l"(p));
    return a;
}
__device__ __forceinline__ uint32_t sw128(uint32_t bo) { return bo ^ ((bo >> 3) & 0x70); }
__device__ __forceinline__ float ex2f(float x) {
    float y; asm("ex2.approx.f32 %0, %1;" : "=f"(y) : "f"(x)); return y;
}
__device__ __forceinline__ uint32_t bfpack(__nv_bfloat16 a, __nv_bfloat16 b) {
    uint16_t x = *reinterpret_cast<uint16_t*>(&a), y = *reinterpret_cast<uint16_t*>(&b);
    return (uint32_t)x | ((uint32_t)y << 16);
}
__device__ __forceinline__ void split1(float f, __nv_bfloat16& h, __nv_bfloat16& l) {
    h = __float2bfloat16(f);
    l = __float2bfloat16(f - __bfloat162float(h));
}

__device__ __forceinline__ void cpa16(uint32_t s, const void* g) {
    asm volatile("cp.async.cg.shared.global [%0], [%1], 16;" :: "r"(s), "l"(g));
}
#define CP_COMMIT() asm volatile("cp.async.commit_group;" ::: "memory")
#define CP_WAIT0()  asm volatile("cp.async.wait_group 0;" ::: "memory")
#define CP_WAIT1()  asm volatile("cp.async.wait_group 1;" ::: "memory")

__device__ __forceinline__ void gcopy(uint32_t sdst, const uint8_t* gsrc,
                                      int bytes, int tid) {
    for (int off = tid * 16; off < bytes; off += TB * 16)
        cpa16(sdst + off, gsrc + off);
}

#define LDSM4(r0,r1,r2,r3,ad) \
    asm volatile("ldmatrix.sync.aligned.m8n8.x4.shared.b16 {%0,%1,%2,%3}, [%4];" \
        : "=r"(r0), "=r"(r1), "=r"(r2), "=r"(r3) : "r"(ad))
#define LDSM4T(r0,r1,r2,r3,ad) \
    asm volatile("ldmatrix.sync.aligned.m8n8.x4.trans.shared.b16 {%0,%1,%2,%3}, [%4];" \
        : "=r"(r0), "=r"(r1), "=r"(r2), "=r"(r3) : "r"(ad))

__device__ __forceinline__ void mma16816(float* c, const uint32_t* a, const uint32_t* b) {
    asm volatile("mma.sync.aligned.m16n8k16.row.col.f32.bf16.bf16.f32 "
        "{%0,%1,%2,%3}, {%4,%5,%6,%7}, {%8,%9}, {%0,%1,%2,%3};"
        : "+f"(c[0]), "+f"(c[1]), "+f"(c[2]), "+f"(c[3])
        : "r"(a[0]), "r"(a[1]), "r"(a[2]), "r"(a[3]), "r"(b[0]), "r"(b[1]));
}

__device__ __forceinline__ void lda_frag(uint32_t* fr, uint32_t tile, int row0, int kbyte) {
    int lane = threadIdx.x & 31;
    int r = row0 + (lane & 7) + (lane & 8);
    int cb = kbyte + ((lane & 16) ? 16 : 0);
    LDSM4(fr[0], fr[1], fr[2], fr[3], tile + sw128((uint32_t)(r * 128 + cb)));
}
__device__ __forceinline__ void ldb_k(uint32_t* fr, uint32_t tile, int n0, int kbyte) {
    int lane = threadIdx.x & 31;
    int r = n0 + (lane & 7) + ((lane & 16) ? 8 : 0);
    int cb = kbyte + ((lane & 8) ? 16 : 0);
    LDSM4(fr[0], fr[1], fr[2], fr[3], tile + sw128((uint32_t)(r * 128 + cb)));
}
__device__ __forceinline__ void ldb_v(uint32_t* fr, uint32_t tile, int k0, int dbyte) {
    int lane = threadIdx.x & 31;
    int r = k0 + (lane & 7) + (lane & 8);
    int cb = dbyte + ((lane & 16) ? 16 : 0);
    LDSM4T(fr[0], fr[1], fr[2], fr[3], tile + sw128((uint32_t)(r * 128 + cb)));
}

// pass-1: 2-product QK (Qh*Kh + Ql*Kh) over 16 rows x 64-col n-half
__device__ __forceinline__ void qk_two(float* sacc, uint32_t qh, uint32_t ql,
                                       uint32_t kh, int wr0, int n0) {
    #pragma unroll
    for (int ks = 0; ks < 4; ks++) {
        uint32_t aH[4], aL[4];
        lda_frag(aH, qh, wr0, ks * 32);
        lda_frag(aL, ql, wr0, ks * 32);
        #pragma unroll
        for (int nb2 = 0; nb2 < 4; nb2++) {
            uint32_t bH[4];
            ldb_k(bH, kh, n0 + nb2 * 16, ks * 32);
            float* c0 = sacc + nb2 * 8;
            mma16816(c0,     aH, bH);     mma16816(c0 + 4, aH, bH + 2);
            mma16816(c0,     aL, bH);     mma16816(c0 + 4, aL, bH + 2);
        }
    }
}
// pass-2: 3-product QK
__device__ __forceinline__ void qk_three(float* sacc, uint32_t qh, uint32_t ql,
                                         uint32_t kh, uint32_t kl, int wr0, int n0) {
    #pragma unroll
    for (int ks = 0; ks < 4; ks++) {
        uint32_t aH[4], aL[4];
        lda_frag(aH, qh, wr0, ks * 32);
        lda_frag(aL, ql, wr0, ks * 32);
        #pragma unroll
        for (int nb2 = 0; nb2 < 4; nb2++) {
            uint32_t bH[4], bL[4];
            ldb_k(bH, kh, n0 + nb2 * 16, ks * 32);
            ldb_k(bL, kl, n0 + nb2 * 16, ks * 32);
            float* c0 = sacc + nb2 * 8;
            mma16816(c0,     aH, bH);     mma16816(c0 + 4, aH, bH + 2);
            mma16816(c0,     aL, bH);     mma16816(c0 + 4, aL, bH + 2);
            mma16816(c0,     aH, bL);     mma16816(c0 + 4, aH, bL + 2);
        }
    }
}

// -------------------------------------------------- pre-convert fp32 -> bf16 hi/lo
__global__ void __launch_bounds__(256)
conv_kernel(const float* __restrict__ q, const float* __restrict__ k,
            const float* __restrict__ v)
{
    const int blk = blockIdx.x, b = blockIdx.y, t = blockIdx.z;
    const float* src = (t == 0 ? q : (t == 1 ? k : v)) + ((size_t)b * NN + blk * 128) * DD;
    uint8_t* dH = g_conv + (((size_t)t * 16 + b) * 16 + blk) * 32768;
    uint8_t* dL = dH + 16384;
    for (int e = threadIdx.x; e < 128 * 16; e += 256) {
        int row = e >> 4, c4 = (e & 15) << 2;
        float4 f = *(const float4*)(src + row * DD + c4);
        __nv_bfloat16 h0,h1,h2,h3,l0,l1,l2,l3;
        split1(f.x,h0,l0); split1(f.y,h1,l1); split1(f.z,h2,l2); split1(f.w,h3,l3);
        uint32_t bo = (uint32_t)(row * 128 + c4 * 2);
        uint32_t s0 = sw128(bo), s1 = sw128(bo + 4);
        *(uint32_t*)(dH + s0) = bfpack(h0, h1);
        *(uint32_t*)(dH + s1) = bfpack(h2, h3);
        *(uint32_t*)(dL + s0) = bfpack(l0, l1);
        *(uint32_t*)(dL + s1) = bfpack(l2, l3);
    }
}

// -------------------------------------------------- main attention kernel
__global__ void __launch_bounds__(TB, 2)
attn_kernel(const float* __restrict__ scp, float* __restrict__ ctx,
            float* __restrict__ att)
{
    extern __shared__ char smem[];
    const uint32_t sb = smem_u32(smem);
    const int tid = threadIdx.x, lane = tid & 31, wid = tid >> 5;
    const int wr0 = (wid >> 1) * 16;       // warp's first q-row (0..48)
    const int nh = wid & 1;                // n-half (== k-half for PV)
    const int n0 = nh * 64;
    const int gr = lane >> 2, c2 = (lane & 3) * 2;
    const int qi = blockIdx.x, b = blockIdx.y, q0 = qi * BM;
    const float cexp = scp[0] * 1.4426950408889634f;

    const uint8_t* qsrc = g_conv + (((size_t)0 * 16 + b) * 16 + (qi >> 1)) * 32768
                        + (size_t)(qi & 1) * 8192;
    const uint8_t* kbase = g_conv + (((size_t)1 * 16 + b) * 16) * 32768;
    const uint8_t* vbase = g_conv + (((size_t)2 * 16 + b) * 16) * 32768;

    // Q panels (8KB hi + 8KB lo) + pass-1 Kh tile 0 -> one commit group
    for (int off = tid * 16; off < 8192; off += TB * 16) {
        cpa16(sb + SM_QH + off, qsrc + off);
        cpa16(sb + SM_QL + off, qsrc + 16384 + off);
    }
    gcopy(sb + ST0, kbase, 16384, tid);
    CP_COMMIT();

    float rs0 = 0.f, rs1 = 0.f;

    // ================= pass 1: row sums (Kh only, 2-product) =================
    for (int kt = 0; kt < NKT; kt++) {
        const uint32_t kst = sb + ST0 + (uint32_t)(kt & 1) * 16384;
        if (kt + 1 < NKT) {
            gcopy(sb + ST0 + (uint32_t)((kt + 1) & 1) * 16384,
                  kbase + (size_t)(kt + 1) * 32768, 16384, tid);
            CP_COMMIT();
            CP_WAIT1();
        } else {
            CP_WAIT0();
        }
        __syncthreads();

        float sacc[32];
        #pragma unroll
        for (int i = 0; i < 32; i++) sacc[i] = 0.f;
        qk_two(sacc, sb + SM_QH, sb + SM_QL, kst, wr0, n0);
        #pragma unroll
        for (int nb = 0; nb < 8; nb++) {
            rs0 += ex2f(sacc[nb*4+0] * cexp) + ex2f(sacc[nb*4+1] * cexp);
            rs1 += ex2f(sacc[nb*4+2] * cexp) + ex2f(sacc[nb*4+3] * cexp);
        }
        __syncthreads();
    }

    // ---- row-sum reduce across the two n-halves ----
    rs0 += __shfl_xor_sync(0xffffffff, rs0, 1);
    rs0 += __shfl_xor_sync(0xffffffff, rs0, 2);
    rs1 += __shfl_xor_sync(0xffffffff, rs1, 1);
    rs1 += __shfl_xor_sync(0xffffffff, rs1, 2);
    float* Ls = (float*)(smem + ST0 + 65536);   // dead area during inter-pass
    if ((lane & 3) == 0) {
        Ls[nh * 64 + wr0 + gr]     = rs0;
        Ls[nh * 64 + wr0 + 8 + gr] = rs1;
    }
    __syncthreads();
    const float li0 = 1.0f / (Ls[wr0 + gr]     + Ls[64 + wr0 + gr]);
    const float li1 = 1.0f / (Ls[wr0 + 8 + gr] + Ls[64 + wr0 + 8 + gr]);
    __syncthreads();

    float oacc[32];
    #pragma unroll
    for (int i = 0; i < 32; i++) oacc[i] = 0.f;

    // ================= pass 2: attention + O =================
    gcopy(sb + ST0,         kbase, 32768, tid);   // K(0) hi+lo
    gcopy(sb + ST0 + 32768, vbase, 32768, tid);   // V(0) hi+lo
    CP_COMMIT();

    for (int kt = 0; kt < NKT; kt++) {
        const uint32_t vst = sb + ST0 + 32768 + (uint32_t)(kt & 1) * 32768;
        if (kt + 1 < NKT) {
            gcopy(sb + ST0 + 32768 + (uint32_t)((kt + 1) & 1) * 32768,
                  vbase + (size_t)(kt + 1) * 32768, 32768, tid);
            CP_COMMIT();
            CP_WAIT1();    // K(t),V(t) landed; V(t+1) in flight
        } else {
            CP_WAIT0();
        }
        __syncthreads();

        float sacc[32];
        #pragma unroll
        for (int i = 0; i < 32; i++) sacc[i] = 0.f;
        qk_three(sacc, sb + SM_QH, sb + SM_QL, sb + ST0, sb + ST0 + 16384, wr0, n0);

        // exp, normalize, write attention, pack P (hi/lo a-frags)
        uint32_t ph[16], pl[16];
        {
            float* arow0 = att + ((size_t)b * NN + q0 + wr0 + gr) * NN + kt * BN + n0 + c2;
            float* arow1 = arow0 + (size_t)8 * NN;
            #pragma unroll
            for (int nb = 0; nb < 8; nb++) {
                float p0 = ex2f(sacc[nb*4+0] * cexp) * li0;
                float p1 = ex2f(sacc[nb*4+1] * cexp) * li0;
                float p2 = ex2f(sacc[nb*4+2] * cexp) * li1;
                float p3 = ex2f(sacc[nb*4+3] * cexp) * li1;
                *(float2*)(arow0 + nb * 8) = make_float2(p0, p1);
                *(float2*)(arow1 + nb * 8) = make_float2(p2, p3);
                __nv_bfloat16 h0,h1,h2,h3,l0,l1,l2,l3;
                split1(p0,h0,l0); split1(p1,h1,l1); split1(p2,h2,l2); split1(p3,h3,l3);
                int ks = nb >> 1, hf2 = (nb & 1) * 2;
                ph[ks*4 + hf2 + 0] = bfpack(h0, h1);
                ph[ks*4 + hf2 + 1] = bfpack(h2, h3);
                pl[ks*4 + hf2 + 0] = bfpack(l0, l1);
                pl[ks*4 + hf2 + 1] = bfpack(l2, l3);
            }
        }
        __syncthreads();   // all warps done reading Kst
        if (kt + 1 < NKT) {
            gcopy(sb + ST0, kbase + (size_t)(kt + 1) * 32768, 32768, tid);  // K(t+1)
            CP_COMMIT();
        }

        // O += P V over this warp's k-half (3-product split)
        #pragma unroll
        for (int ks = 0; ks < 4; ks++) {
            const uint32_t* aH = ph + ks * 4;
            const uint32_t* aL = pl + ks * 4;
            const int k0 = n0 + ks * 16;
            #pragma unroll
            for (int db2 = 0; db2 < 4; db2++) {
                uint32_t bH[4], bL[4];
                ldb_v(bH, vst,         k0, db2 * 32);
                ldb_v(bL, vst + 16384, k0, db2 * 32);
                float* c0 = oacc + db2 * 8;
                mma16816(c0,     aH, bH);     mma16816(c0 + 4, aH, bH + 2);
                mma16816(c0,     aL, bH);     mma16816(c0 + 4, aL, bH + 2);
                mma16816(c0,     aH, bL);     mma16816(c0 + 4, aH, bL + 2);
            }
        }
        __syncthreads();   // V stage (kt&1) free for the t+2 prefetch
    }

    // ---- reduce O across nh warp-pairs, write context ----
    {
        char* red = smem + ST0 + (size_t)(wid >> 1) * 4096;   // stage area, dead
        if (nh == 1) {
            #pragma unroll
            for (int db = 0; db < 8; db++) {
                *(float2*)(red + ((uint32_t)(gr)     * 64 + db * 8 + c2) * 4) =
                    make_float2(oacc[db*4+0], oacc[db*4+1]);
                *(float2*)(red + ((uint32_t)(gr + 8) * 64 + db * 8 + c2) * 4) =
                    make_float2(oacc[db*4+2], oacc[db*4+3]);
            }
        }
        __syncthreads();
        if (nh == 0) {
            float* crow0 = ctx + ((size_t)b * NN + q0 + wr0 + gr) * DD + c2;
            float* crow1 = crow0 + 8 * DD;
            #pragma unroll
            for (int db = 0; db < 8; db++) {
                float2 a0 = *(float2*)(red + ((uint32_t)(gr)     * 64 + db * 8 + c2) * 4);
                float2 a1 = *(float2*)(red + ((uint32_t)(gr + 8) * 64 + db * 8 + c2) * 4);
                *(float2*)(crow0 + db * 8) = make_float2(oacc[db*4+0] + a0.x, oacc[db*4+1] + a0.y);
                *(float2*)(crow1 + db * 8) = make_float2(oacc[db*4+2] + a1.x, oacc[db*4+3] + a1.y);
            }
        }
    }
}

extern "C" void kernel_launch(void* const* d_in, const int* in_sizes, int n_in,
                              void* d_out, int out_size) {
    const float* q  = (const float*)d_in[0];
    const float* k  = (const float*)d_in[1];
    const float* v  = (const float*)d_in[2];
    const float* sc = (const float*)d_in[3];
    float* ctx = (float*)d_out;                          // [16,2048,64]
    float* att = (float*)d_out + (size_t)NB * NN * DD;   // [16,2048,2048]

    conv_kernel<<<dim3(16, NB, 3), 256>>>(q, k, v);

    cudaFuncSetAttribute(attn_kernel, cudaFuncAttributeMaxDynamicSharedMemorySize, SMEM_TOTAL);
    dim3 grid(NN / BM, NB);
    attn_kernel<<<grid, TB, SMEM_TOTAL>>>(sc, ctx, att);
}

// round 10
// speedup vs baseline: 1.2468x; 1.2468x over previous
#include <cuda_runtime.h>
#include <cuda_fp16.h>
#include <cstdint>

static constexpr int NB = 16, NN = 2048, DD = 64;
static constexpr int BM = 128, BN = 128, NKT = NN / BN, TB = 512;

// Pre-converted fp16 hi/lo panels, SW128-swizzled, 128-row blocks:
// g_conv[(t*16 + b)*16 + blk] -> 32KB {hi 16KB, lo 16KB}, t: 0=Q,1=K,2=V
__device__ __align__(128) uint8_t g_conv[(size_t)3 * 16 * 16 * 32768];

// SMEM:
//   QH 16K @0, QL 16K @16384
//   ST0=32768:
//     pass1: Kh stage s @ ST0 + s*16384
//     pass2: Kh @ ST0, Kl @ ST0+16384; Vh stage s @ ST0+32768+s*16384
//   SM_L = ST0+65536 row-sum scratch; O-reduce reuses ST0 area at the end
static constexpr int SM_QH = 0, SM_QL = 16384;
static constexpr int ST0 = 32768;
static constexpr int SM_L = ST0 + 65536;          // 98304
static constexpr int SMEM_TOTAL = SM_L + 1024;    // 99328

__device__ __forceinline__ uint32_t smem_u32(const void* p) {
    uint32_t a;
    asm("{ .reg .u64 t; cvta.to.shared.u64 t, %1; cvt.u32.u64 %0, t; }" : "=r"(a) : "l"(p));
    return a;
}
__device__ __forceinline__ uint32_t sw128(uint32_t bo) { return bo ^ ((bo >> 3) & 0x70); }
__device__ __forceinline__ float ex2f(float x) {
    float y; asm("ex2.approx.f32 %0, %1;" : "=f"(y) : "f"(x)); return y;
}
__device__ __forceinline__ uint32_t hpack(float a, float b) {
    __half2 h = __floats2half2_rn(a, b);
    return *reinterpret_cast<uint32_t*>(&h);
}
__device__ __forceinline__ void split1h(float f, __half& h, __half& l) {
    h = __float2half_rn(f);
    l = __float2half_rn(f - __half2float(h));
}

__device__ __forceinline__ void cpa16(uint32_t s, const void* g) {
    asm volatile("cp.async.cg.shared.global [%0], [%1], 16;" :: "r"(s), "l"(g));
}
#define CP_COMMIT() asm volatile("cp.async.commit_group;" ::: "memory")
#define CP_WAIT0()  asm volatile("cp.async.wait_group 0;" ::: "memory")
#define CP_WAIT1()  asm volatile("cp.async.wait_group 1;" ::: "memory")

__device__ __forceinline__ void gcopy(uint32_t sdst, const uint8_t* gsrc,
                                      int bytes, int tid) {
    for (int off = tid * 16; off < bytes; off += TB * 16)
        cpa16(sdst + off, gsrc + off);
}

#define LDSM4(r0,r1,r2,r3,ad) \
    asm volatile("ldmatrix.sync.aligned.m8n8.x4.shared.b16 {%0,%1,%2,%3}, [%4];" \
        : "=r"(r0), "=r"(r1), "=r"(r2), "=r"(r3) : "r"(ad))
#define LDSM4T(r0,r1,r2,r3,ad) \
    asm volatile("ldmatrix.sync.aligned.m8n8.x4.trans.shared.b16 {%0,%1,%2,%3}, [%4];" \
        : "=r"(r0), "=r"(r1), "=r"(r2), "=r"(r3) : "r"(ad))

__device__ __forceinline__ void mma16816(float* c, const uint32_t* a, const uint32_t* b) {
    asm volatile("mma.sync.aligned.m16n8k16.row.col.f32.f16.f16.f32 "
        "{%0,%1,%2,%3}, {%4,%5,%6,%7}, {%8,%9}, {%0,%1,%2,%3};"
        : "+f"(c[0]), "+f"(c[1]), "+f"(c[2]), "+f"(c[3])
        : "r"(a[0]), "r"(a[1]), "r"(a[2]), "r"(a[3]), "r"(b[0]), "r"(b[1]));
}

__device__ __forceinline__ void lda_frag(uint32_t* fr, uint32_t tile, int row0, int kbyte) {
    int lane = threadIdx.x & 31;
    int r = row0 + (lane & 7) + (lane & 8);
    int cb = kbyte + ((lane & 16) ? 16 : 0);
    LDSM4(fr[0], fr[1], fr[2], fr[3], tile + sw128((uint32_t)(r * 128 + cb)));
}
__device__ __forceinline__ void ldb_k(uint32_t* fr, uint32_t tile, int n0, int kbyte) {
    int lane = threadIdx.x & 31;
    int r = n0 + (lane & 7) + ((lane & 16) ? 8 : 0);
    int cb = kbyte + ((lane & 8) ? 16 : 0);
    LDSM4(fr[0], fr[1], fr[2], fr[3], tile + sw128((uint32_t)(r * 128 + cb)));
}
__device__ __forceinline__ void ldb_v(uint32_t* fr, uint32_t tile, int k0, int dbyte) {
    int lane = threadIdx.x & 31;
    int r = k0 + (lane & 7) + (lane & 8);
    int cb = dbyte + ((lane & 16) ? 16 : 0);
    LDSM4T(fr[0], fr[1], fr[2], fr[3], tile + sw128((uint32_t)(r * 128 + cb)));
}

// pass-1: 1-product QK (Qh*Kh) over 16 rows x 64-col n-half
__device__ __forceinline__ void qk_one(float* sacc, uint32_t qh, uint32_t kh,
                                       int wr0, int n0) {
    #pragma unroll
    for (int ks = 0; ks < 4; ks++) {
        uint32_t aH[4];
        lda_frag(aH, qh, wr0, ks * 32);
        #pragma unroll
        for (int nb2 = 0; nb2 < 4; nb2++) {
            uint32_t bH[4];
            ldb_k(bH, kh, n0 + nb2 * 16, ks * 32);
            float* c0 = sacc + nb2 * 8;
            mma16816(c0, aH, bH);     mma16816(c0 + 4, aH, bH + 2);
        }
    }
}
// pass-2: 3-product QK (full precision for attention output)
__device__ __forceinline__ void qk_three(float* sacc, uint32_t qh, uint32_t ql,
                                         uint32_t kh, uint32_t kl, int wr0, int n0) {
    #pragma unroll
    for (int ks = 0; ks < 4; ks++) {
        uint32_t aH[4], aL[4];
        lda_frag(aH, qh, wr0, ks * 32);
        lda_frag(aL, ql, wr0, ks * 32);
        #pragma unroll
        for (int nb2 = 0; nb2 < 4; nb2++) {
            uint32_t bH[4], bL[4];
            ldb_k(bH, kh, n0 + nb2 * 16, ks * 32);
            ldb_k(bL, kl, n0 + nb2 * 16, ks * 32);
            float* c0 = sacc + nb2 * 8;
            mma16816(c0,     aH, bH);     mma16816(c0 + 4, aH, bH + 2);
            mma16816(c0,     aL, bH);     mma16816(c0 + 4, aL, bH + 2);
            mma16816(c0,     aH, bL);     mma16816(c0 + 4, aH, bL + 2);
        }
    }
}

// -------------------------------------------------- pre-convert fp32 -> fp16 hi/lo
__global__ void __launch_bounds__(256)
conv_kernel(const float* __restrict__ q, const float* __restrict__ k,
            const float* __restrict__ v)
{
    const int blk = blockIdx.x, b = blockIdx.y, t = blockIdx.z;
    const float* src = (t == 0 ? q : (t == 1 ? k : v)) + ((size_t)b * NN + blk * 128) * DD;
    uint8_t* dH = g_conv + (((size_t)t * 16 + b) * 16 + blk) * 32768;
    uint8_t* dL = dH + 16384;
    for (int e = threadIdx.x; e < 128 * 16; e += 256) {
        int row = e >> 4, c4 = (e & 15) << 2;
        float4 f = *(const float4*)(src + row * DD + c4);
        __half h0,h1,h2,h3,l0,l1,l2,l3;
        split1h(f.x,h0,l0); split1h(f.y,h1,l1); split1h(f.z,h2,l2); split1h(f.w,h3,l3);
        uint32_t bo = (uint32_t)(row * 128 + c4 * 2);
        uint32_t s0 = sw128(bo), s1 = sw128(bo + 4);
        __half2 p01 = __halves2half2(h0, h1), p23 = __halves2half2(h2, h3);
        __half2 q01 = __halves2half2(l0, l1), q23 = __halves2half2(l2, l3);
        *(uint32_t*)(dH + s0) = *reinterpret_cast<uint32_t*>(&p01);
        *(uint32_t*)(dH + s1) = *reinterpret_cast<uint32_t*>(&p23);
        *(uint32_t*)(dL + s0) = *reinterpret_cast<uint32_t*>(&q01);
        *(uint32_t*)(dL + s1) = *reinterpret_cast<uint32_t*>(&q23);
    }
}

// -------------------------------------------------- main attention kernel
__global__ void __launch_bounds__(TB, 1)
attn_kernel(const float* __restrict__ scp, float* __restrict__ ctx,
            float* __restrict__ att)
{
    extern __shared__ char smem[];
    const uint32_t sb = smem_u32(smem);
    const int tid = threadIdx.x, lane = tid & 31, wid = tid >> 5;
    const int wr0 = (wid >> 1) * 16;       // warp's first q-row (0..112)
    const int nh = wid & 1;                // n-half (== k-half for PV)
    const int n0 = nh * 64;
    const int gr = lane >> 2, c2 = (lane & 3) * 2;
    const int b = blockIdx.y, q0 = blockIdx.x * BM;
    const float cexp = scp[0] * 1.4426950408889634f;

    const uint8_t* qblk = g_conv + (((size_t)0 * 16 + b) * 16 + blockIdx.x) * 32768;
    const uint8_t* kbase = g_conv + (((size_t)1 * 16 + b) * 16) * 32768;
    const uint8_t* vbase = g_conv + (((size_t)2 * 16 + b) * 16) * 32768;

    // Q panels (32KB) + pass-1 Kh(0): one commit group
    gcopy(sb + SM_QH, qblk, 32768, tid);
    gcopy(sb + ST0, kbase, 16384, tid);
    CP_COMMIT();

    float rs0 = 0.f, rs1 = 0.f;

    // ================= pass 1: row sums (Qh*Kh) =================
    for (int kt = 0; kt < NKT; kt++) {
        const uint32_t kst = sb + ST0 + (uint32_t)(kt & 1) * 16384;
        if (kt + 1 < NKT) {
            gcopy(sb + ST0 + (uint32_t)((kt + 1) & 1) * 16384,
                  kbase + (size_t)(kt + 1) * 32768, 16384, tid);
            CP_COMMIT();
            CP_WAIT1();
        } else {
            CP_WAIT0();
        }
        __syncthreads();

        float sacc[32];
        #pragma unroll
        for (int i = 0; i < 32; i++) sacc[i] = 0.f;
        qk_one(sacc, sb + SM_QH, kst, wr0, n0);
        #pragma unroll
        for (int nb = 0; nb < 8; nb++) {
            rs0 += ex2f(sacc[nb*4+0] * cexp) + ex2f(sacc[nb*4+1] * cexp);
            rs1 += ex2f(sacc[nb*4+2] * cexp) + ex2f(sacc[nb*4+3] * cexp);
        }
        __syncthreads();
    }

    // ---- row-sum reduce across the two n-halves ----
    rs0 += __shfl_xor_sync(0xffffffff, rs0, 1);
    rs0 += __shfl_xor_sync(0xffffffff, rs0, 2);
    rs1 += __shfl_xor_sync(0xffffffff, rs1, 1);
    rs1 += __shfl_xor_sync(0xffffffff, rs1, 2);
    float* Ls = (float*)(smem + SM_L);
    if ((lane & 3) == 0) {
        Ls[nh * 128 + wr0 + gr]     = rs0;
        Ls[nh * 128 + wr0 + 8 + gr] = rs1;
    }
    __syncthreads();
    const float li0 = 1.0f / (Ls[wr0 + gr]     + Ls[128 + wr0 + gr]);
    const float li1 = 1.0f / (Ls[wr0 + 8 + gr] + Ls[128 + wr0 + 8 + gr]);
    __syncthreads();

    float oacc[32];
    #pragma unroll
    for (int i = 0; i < 32; i++) oacc[i] = 0.f;

    // ================= pass 2: attention + O =================
    gcopy(sb + ST0,         kbase, 32768, tid);   // K(0) hi+lo
    gcopy(sb + ST0 + 32768, vbase, 16384, tid);   // Vh(0)
    CP_COMMIT();

    for (int kt = 0; kt < NKT; kt++) {
        const uint32_t vst = sb + ST0 + 32768 + (uint32_t)(kt & 1) * 16384;
        if (kt + 1 < NKT) {
            gcopy(sb + ST0 + 32768 + (uint32_t)((kt + 1) & 1) * 16384,
                  vbase + (size_t)(kt + 1) * 32768, 16384, tid);
            CP_COMMIT();
            CP_WAIT1();    // K(t), Vh(t) landed; Vh(t+1) in flight
        } else {
            CP_WAIT0();
        }
        __syncthreads();

        float sacc[32];
        #pragma unroll
        for (int i = 0; i < 32; i++) sacc[i] = 0.f;
        qk_three(sacc, sb + SM_QH, sb + SM_QL, sb + ST0, sb + ST0 + 16384, wr0, n0);

        // exp (unnormalized), write normalized att, pack e -> fp16 a-frags
        uint32_t ph[16];
        {
            float* arow0 = att + ((size_t)b * NN + q0 + wr0 + gr) * NN + kt * BN + n0 + c2;
            float* arow1 = arow0 + (size_t)8 * NN;
            #pragma unroll
            for (int nb = 0; nb < 8; nb++) {
                float e0 = ex2f(sacc[nb*4+0] * cexp);
                float e1 = ex2f(sacc[nb*4+1] * cexp);
                float e2 = ex2f(sacc[nb*4+2] * cexp);
                float e3 = ex2f(sacc[nb*4+3] * cexp);
                *(float2*)(arow0 + nb * 8) = make_float2(e0 * li0, e1 * li0);
                *(float2*)(arow1 + nb * 8) = make_float2(e2 * li1, e3 * li1);
                int ks = nb >> 1, hf2 = (nb & 1) * 2;
                ph[ks*4 + hf2 + 0] = hpack(e0, e1);
                ph[ks*4 + hf2 + 1] = hpack(e2, e3);
            }
        }
        __syncthreads();   // all warps done reading K stage
        if (kt + 1 < NKT) {
            gcopy(sb + ST0, kbase + (size_t)(kt + 1) * 32768, 32768, tid);  // K(t+1)
            CP_COMMIT();
        }

        // O_unnorm += e * Vh over this warp's k-half (1-product)
        #pragma unroll
        for (int ks = 0; ks < 4; ks++) {
            const uint32_t* aH = ph + ks * 4;
            const int k0 = n0 + ks * 16;
            #pragma unroll
            for (int db2 = 0; db2 < 4; db2++) {
                uint32_t bH[4];
                ldb_v(bH, vst, k0, db2 * 32);
                float* c0 = oacc + db2 * 8;
                mma16816(c0, aH, bH);     mma16816(c0 + 4, aH, bH + 2);
            }
        }
        __syncthreads();   // V stage (kt&1) free for the t+2 prefetch
    }

    // ---- normalize O, reduce across nh warp-pairs, write context ----
    #pragma unroll
    for (int db = 0; db < 8; db++) {
        oacc[db*4+0] *= li0;  oacc[db*4+1] *= li0;
        oacc[db*4+2] *= li1;  oacc[db*4+3] *= li1;
    }
    {
        char* red = smem + ST0 + (size_t)(wid >> 1) * 4096;   // K/V area, dead now
        if (nh == 1) {
            #pragma unroll
            for (int db = 0; db < 8; db++) {
                *(float2*)(red + ((uint32_t)(gr)     * 64 + db * 8 + c2) * 4) =
                    make_float2(oacc[db*4+0], oacc[db*4+1]);
                *(float2*)(red + ((uint32_t)(gr + 8) * 64 + db * 8 + c2) * 4) =
                    make_float2(oacc[db*4+2], oacc[db*4+3]);
            }
        }
        __syncthreads();
        if (nh == 0) {
            float* crow0 = ctx + ((size_t)b * NN + q0 + wr0 + gr) * DD + c2;
            float* crow1 = crow0 + 8 * DD;
            #pragma unroll
            for (int db = 0; db < 8; db++) {
                float2 a0 = *(float2*)(red + ((uint32_t)(gr)     * 64 + db * 8 + c2) * 4);
                float2 a1 = *(float2*)(red + ((uint32_t)(gr + 8) * 64 + db * 8 + c2) * 4);
                *(float2*)(crow0 + db * 8) = make_float2(oacc[db*4+0] + a0.x, oacc[db*4+1] + a0.y);
                *(float2*)(crow1 + db * 8) = make_float2(oacc[db*4+2] + a1.x, oacc[db*4+3] + a1.y);
            }
        }
    }
}

extern "C" void kernel_launch(void* const* d_in, const int* in_sizes, int n_in,
                              void* d_out, int out_size) {
    const float* q  = (const float*)d_in[0];
    const float* k  = (const float*)d_in[1];
    const float* v  = (const float*)d_in[2];
    const float* sc = (const float*)d_in[3];
    float* ctx = (float*)d_out;                          // [16,2048,64]
    float* att = (float*)d_out + (size_t)NB * NN * DD;   // [16,2048,2048]

    conv_kernel<<<dim3(16, NB, 3), 256>>>(q, k, v);

    cudaFuncSetAttribute(attn_kernel, cudaFuncAttributeMaxDynamicSharedMemorySize, SMEM_TOTAL);
    dim3 grid(NN / BM, NB);
    attn_kernel<<<grid, TB, SMEM_TOTAL>>>(sc, ctx, att);
}

// round 11
// speedup vs baseline: 1.3022x; 1.0444x over previous
#include <cuda_runtime.h>
#include <cuda_fp16.h>
#include <cstdint>

static constexpr int NB = 16, NN = 2048, DD = 64;
static constexpr int BM = 128, BN = 128, NKT = NN / BN, TB = 512;

// Pre-converted fp16 hi/lo panels, SW128-swizzled, 128-row blocks:
// g_conv[(t*16 + b)*16 + blk] -> 32KB {hi 16KB, lo 16KB}, t: 0=Q,1=K,2=V
__device__ __align__(128) uint8_t g_conv[(size_t)3 * 16 * 16 * 32768];

// SMEM:
//   QH 16K @0, QL 16K @16384
//   ST0=32768: 3-stage ring, stride STG3=48KB: {Kh 16K, Kl 16K, Vh 16K}
//     (pass 1 uses the same ring with 16KB Kh-only stages)
//   SM_L row-sum scratch; final O-reduce reuses the ring area
static constexpr int SM_QH = 0, SM_QL = 16384;
static constexpr int ST0 = 32768, STG3 = 49152;
static constexpr int SM_L = ST0 + 3 * STG3;       // 180224
static constexpr int SMEM_TOTAL = SM_L + 1024;    // 181248

__device__ __forceinline__ uint32_t smem_u32(const void* p) {
    uint32_t a;
    asm("{ .reg .u64 t; cvta.to.shared.u64 t, %1; cvt.u32.u64 %0, t; }" : "=r"(a) : "l"(p));
    return a;
}
__device__ __forceinline__ uint32_t sw128(uint32_t bo) { return bo ^ ((bo >> 3) & 0x70); }
__device__ __forceinline__ float ex2f(float x) {
    float y; asm("ex2.approx.f32 %0, %1;" : "=f"(y) : "f"(x)); return y;
}
__device__ __forceinline__ uint32_t hpack(float a, float b) {
    __half2 h = __floats2half2_rn(a, b);
    return *reinterpret_cast<uint32_t*>(&h);
}
__device__ __forceinline__ void split1h(float f, __half& h, __half& l) {
    h = __float2half_rn(f);
    l = __float2half_rn(f - __half2float(h));
}

__device__ __forceinline__ void cpa16(uint32_t s, const void* g) {
    asm volatile("cp.async.cg.shared.global [%0], [%1], 16;" :: "r"(s), "l"(g));
}
#define CP_COMMIT() asm volatile("cp.async.commit_group;" ::: "memory")
#define CP_WAIT0()  asm volatile("cp.async.wait_group 0;" ::: "memory")
#define CP_WAIT1()  asm volatile("cp.async.wait_group 1;" ::: "memory")

__device__ __forceinline__ void gcopy(uint32_t sdst, const uint8_t* gsrc,
                                      int bytes, int tid) {
    for (int off = tid * 16; off < bytes; off += TB * 16)
        cpa16(sdst + off, gsrc + off);
}

#define LDSM4(r0,r1,r2,r3,ad) \
    asm volatile("ldmatrix.sync.aligned.m8n8.x4.shared.b16 {%0,%1,%2,%3}, [%4];" \
        : "=r"(r0), "=r"(r1), "=r"(r2), "=r"(r3) : "r"(ad))
#define LDSM4T(r0,r1,r2,r3,ad) \
    asm volatile("ldmatrix.sync.aligned.m8n8.x4.trans.shared.b16 {%0,%1,%2,%3}, [%4];" \
        : "=r"(r0), "=r"(r1), "=r"(r2), "=r"(r3) : "r"(ad))

__device__ __forceinline__ void mma16816(float* c, const uint32_t* a, const uint32_t* b) {
    asm volatile("mma.sync.aligned.m16n8k16.row.col.f32.f16.f16.f32 "
        "{%0,%1,%2,%3}, {%4,%5,%6,%7}, {%8,%9}, {%0,%1,%2,%3};"
        : "+f"(c[0]), "+f"(c[1]), "+f"(c[2]), "+f"(c[3])
        : "r"(a[0]), "r"(a[1]), "r"(a[2]), "r"(a[3]), "r"(b[0]), "r"(b[1]));
}

__device__ __forceinline__ void lda_frag(uint32_t* fr, uint32_t tile, int row0, int kbyte) {
    int lane = threadIdx.x & 31;
    int r = row0 + (lane & 7) + (lane & 8);
    int cb = kbyte + ((lane & 16) ? 16 : 0);
    LDSM4(fr[0], fr[1], fr[2], fr[3], tile + sw128((uint32_t)(r * 128 + cb)));
}
__device__ __forceinline__ void ldb_k(uint32_t* fr, uint32_t tile, int n0, int kbyte) {
    int lane = threadIdx.x & 31;
    int r = n0 + (lane & 7) + ((lane & 16) ? 8 : 0);
    int cb = kbyte + ((lane & 8) ? 16 : 0);
    LDSM4(fr[0], fr[1], fr[2], fr[3], tile + sw128((uint32_t)(r * 128 + cb)));
}
__device__ __forceinline__ void ldb_v(uint32_t* fr, uint32_t tile, int k0, int dbyte) {
    int lane = threadIdx.x & 31;
    int r = k0 + (lane & 7) + (lane & 8);
    int cb = dbyte + ((lane & 16) ? 16 : 0);
    LDSM4T(fr[0], fr[1], fr[2], fr[3], tile + sw128((uint32_t)(r * 128 + cb)));
}

// pass-2: 3-product QK (full precision for attention output)
__device__ __forceinline__ void qk_three(float* sacc, uint32_t qh, uint32_t ql,
                                         uint32_t kh, uint32_t kl, int wr0, int n0) {
    #pragma unroll
    for (int ks = 0; ks < 4; ks++) {
        uint32_t aH[4], aL[4];
        lda_frag(aH, qh, wr0, ks * 32);
        lda_frag(aL, ql, wr0, ks * 32);
        #pragma unroll
        for (int nb2 = 0; nb2 < 4; nb2++) {
            uint32_t bH[4], bL[4];
            ldb_k(bH, kh, n0 + nb2 * 16, ks * 32);
            ldb_k(bL, kl, n0 + nb2 * 16, ks * 32);
            float* c0 = sacc + nb2 * 8;
            mma16816(c0,     aH, bH);     mma16816(c0 + 4, aH, bH + 2);
            mma16816(c0,     aL, bH);     mma16816(c0 + 4, aL, bH + 2);
            mma16816(c0,     aH, bL);     mma16816(c0 + 4, aH, bL + 2);
        }
    }
}

// -------------------------------------------------- pre-convert fp32 -> fp16 hi/lo
__global__ void __launch_bounds__(256)
conv_kernel(const float* __restrict__ q, const float* __restrict__ k,
            const float* __restrict__ v)
{
    const int blk = blockIdx.x, b = blockIdx.y, t = blockIdx.z;
    const float* src = (t == 0 ? q : (t == 1 ? k : v)) + ((size_t)b * NN + blk * 128) * DD;
    uint8_t* dH = g_conv + (((size_t)t * 16 + b) * 16 + blk) * 32768;
    uint8_t* dL = dH + 16384;
    for (int e = threadIdx.x; e < 128 * 16; e += 256) {
        int row = e >> 4, c4 = (e & 15) << 2;
        float4 f = *(const float4*)(src + row * DD + c4);
        __half h0,h1,h2,h3,l0,l1,l2,l3;
        split1h(f.x,h0,l0); split1h(f.y,h1,l1); split1h(f.z,h2,l2); split1h(f.w,h3,l3);
        uint32_t bo = (uint32_t)(row * 128 + c4 * 2);
        uint32_t s0 = sw128(bo), s1 = sw128(bo + 4);
        __half2 p01 = __halves2half2(h0, h1), p23 = __halves2half2(h2, h3);
        __half2 q01 = __halves2half2(l0, l1), q23 = __halves2half2(l2, l3);
        *(uint32_t*)(dH + s0) = *reinterpret_cast<uint32_t*>(&p01);
        *(uint32_t*)(dH + s1) = *reinterpret_cast<uint32_t*>(&p23);
        *(uint32_t*)(dL + s0) = *reinterpret_cast<uint32_t*>(&q01);
        *(uint32_t*)(dL + s1) = *reinterpret_cast<uint32_t*>(&q23);
    }
}

// -------------------------------------------------- main attention kernel
__global__ void __launch_bounds__(TB, 1)
attn_kernel(const float* __restrict__ scp, float* __restrict__ ctx,
            float* __restrict__ att)
{
    extern __shared__ char smem[];
    const uint32_t sb = smem_u32(smem);
    const int tid = threadIdx.x, lane = tid & 31, wid = tid >> 5;
    const int wr0 = (wid >> 1) * 16;       // warp's first q-row (0..112)
    const int nh = wid & 1;                // n-half (== k-half for PV)
    const int n0 = nh * 64;
    const int gr = lane >> 2, c2 = (lane & 3) * 2;
    const int b = blockIdx.y, q0 = blockIdx.x * BM;
    const float cexp = scp[0] * 1.4426950408889634f;

    const uint8_t* qblk = g_conv + (((size_t)0 * 16 + b) * 16 + blockIdx.x) * 32768;
    const uint8_t* kbase = g_conv + (((size_t)1 * 16 + b) * 16) * 32768;
    const uint8_t* vbase = g_conv + (((size_t)2 * 16 + b) * 16) * 32768;

    // prologue: group0 = Q panels + Kh(0); group1 = Kh(1)
    gcopy(sb + SM_QH, qblk, 32768, tid);
    gcopy(sb + ST0, kbase, 16384, tid);
    CP_COMMIT();
    gcopy(sb + ST0 + STG3, kbase + 32768, 16384, tid);
    CP_COMMIT();

    float rs0 = 0.f, rs1 = 0.f;
    uint32_t aP1[16];   // pass-1 Q-hi fragments, persistent across tiles

    // ================= pass 1: row sums (Qh*Kh, 3-stage ring) =================
    for (int kt = 0; kt < NKT; kt++) {
        if (kt + 1 < NKT) { CP_WAIT1(); } else { CP_WAIT0(); }
        __syncthreads();
        if (kt + 2 < NKT) {
            gcopy(sb + ST0 + (uint32_t)((kt + 2) % 3) * STG3,
                  kbase + (size_t)(kt + 2) * 32768, 16384, tid);
            CP_COMMIT();
        }
        if (kt == 0) {
            #pragma unroll
            for (int ks = 0; ks < 4; ks++)
                lda_frag(aP1 + ks * 4, sb + SM_QH, wr0, ks * 32);
        }
        const uint32_t kst = sb + ST0 + (uint32_t)(kt % 3) * STG3;
        float sacc[32];
        #pragma unroll
        for (int i = 0; i < 32; i++) sacc[i] = 0.f;
        #pragma unroll
        for (int ks = 0; ks < 4; ks++) {
            #pragma unroll
            for (int nb2 = 0; nb2 < 4; nb2++) {
                uint32_t bH[4];
                ldb_k(bH, kst, n0 + nb2 * 16, ks * 32);
                float* c0 = sacc + nb2 * 8;
                mma16816(c0, aP1 + ks*4, bH);  mma16816(c0 + 4, aP1 + ks*4, bH + 2);
            }
        }
        #pragma unroll
        for (int nb = 0; nb < 8; nb++) {
            rs0 += ex2f(sacc[nb*4+0] * cexp) + ex2f(sacc[nb*4+1] * cexp);
            rs1 += ex2f(sacc[nb*4+2] * cexp) + ex2f(sacc[nb*4+3] * cexp);
        }
    }

    // ---- row-sum reduce across the two n-halves ----
    rs0 += __shfl_xor_sync(0xffffffff, rs0, 1);
    rs0 += __shfl_xor_sync(0xffffffff, rs0, 2);
    rs1 += __shfl_xor_sync(0xffffffff, rs1, 1);
    rs1 += __shfl_xor_sync(0xffffffff, rs1, 2);
    float* Ls = (float*)(smem + SM_L);
    __syncthreads();          // all pass-1 stage reads done
    if ((lane & 3) == 0) {
        Ls[nh * 128 + wr0 + gr]     = rs0;
        Ls[nh * 128 + wr0 + 8 + gr] = rs1;
    }
    __syncthreads();
    const float li0 = 1.0f / (Ls[wr0 + gr]     + Ls[128 + wr0 + gr]);
    const float li1 = 1.0f / (Ls[wr0 + 8 + gr] + Ls[128 + wr0 + 8 + gr]);

    float oacc[32];
    #pragma unroll
    for (int i = 0; i < 32; i++) oacc[i] = 0.f;

    // ================= pass 2: attention + O (3-stage ring) =================
    // stage layout: Kh @ +0, Kl @ +16384, Vh @ +32768
    {
        uint32_t s0a = sb + ST0;
        gcopy(s0a,          kbase, 32768, tid);
        gcopy(s0a + 32768,  vbase, 16384, tid);
        CP_COMMIT();
        uint32_t s1a = sb + ST0 + STG3;
        gcopy(s1a,          kbase + 32768, 32768, tid);
        gcopy(s1a + 32768,  vbase + 32768, 16384, tid);
        CP_COMMIT();
    }

    for (int kt = 0; kt < NKT; kt++) {
        if (kt + 1 < NKT) { CP_WAIT1(); } else { CP_WAIT0(); }
        __syncthreads();
        if (kt + 2 < NKT) {
            uint32_t sa = sb + ST0 + (uint32_t)((kt + 2) % 3) * STG3;
            gcopy(sa,         kbase + (size_t)(kt + 2) * 32768, 32768, tid);
            gcopy(sa + 32768, vbase + (size_t)(kt + 2) * 32768, 16384, tid);
            CP_COMMIT();
        }
        const uint32_t stg = sb + ST0 + (uint32_t)(kt % 3) * STG3;
        const uint32_t vst = stg + 32768;

        float sacc[32];
        #pragma unroll
        for (int i = 0; i < 32; i++) sacc[i] = 0.f;
        qk_three(sacc, sb + SM_QH, sb + SM_QL, stg, stg + 16384, wr0, n0);

        // interleaved: per ks -> epilogue(2 nb blocks) then PV(ks)
        float* arow0 = att + ((size_t)b * NN + q0 + wr0 + gr) * NN + kt * BN + n0 + c2;
        float* arow1 = arow0 + (size_t)8 * NN;
        #pragma unroll
        for (int ks = 0; ks < 4; ks++) {
            uint32_t ph[4];
            #pragma unroll
            for (int j = 0; j < 2; j++) {
                const int nb = 2 * ks + j;
                float e0 = ex2f(sacc[nb*4+0] * cexp);
                float e1 = ex2f(sacc[nb*4+1] * cexp);
                float e2 = ex2f(sacc[nb*4+2] * cexp);
                float e3 = ex2f(sacc[nb*4+3] * cexp);
                *(float2*)(arow0 + nb * 8) = make_float2(e0 * li0, e1 * li0);
                *(float2*)(arow1 + nb * 8) = make_float2(e2 * li1, e3 * li1);
                ph[j*2 + 0] = hpack(e0, e1);
                ph[j*2 + 1] = hpack(e2, e3);
            }
            const int k0 = n0 + ks * 16;
            #pragma unroll
            for (int db2 = 0; db2 < 4; db2++) {
                uint32_t bH[4];
                ldb_v(bH, vst, k0, db2 * 32);
                float* c0 = oacc + db2 * 8;
                mma16816(c0, ph, bH);     mma16816(c0 + 4, ph, bH + 2);
            }
        }
    }

    // ---- normalize O, reduce across nh warp-pairs, write context ----
    #pragma unroll
    for (int db = 0; db < 8; db++) {
        oacc[db*4+0] *= li0;  oacc[db*4+1] *= li0;
        oacc[db*4+2] *= li1;  oacc[db*4+3] *= li1;
    }
    __syncthreads();   // all stage reads done; ring area reusable
    {
        char* red = smem + ST0 + (size_t)(wid >> 1) * 4096;
        if (nh == 1) {
            #pragma unroll
            for (int db = 0; db < 8; db++) {
                *(float2*)(red + ((uint32_t)(gr)     * 64 + db * 8 + c2) * 4) =
                    make_float2(oacc[db*4+0], oacc[db*4+1]);
                *(float2*)(red + ((uint32_t)(gr + 8) * 64 + db * 8 + c2) * 4) =
                    make_float2(oacc[db*4+2], oacc[db*4+3]);
            }
        }
        __syncthreads();
        if (nh == 0) {
            float* crow0 = ctx + ((size_t)b * NN + q0 + wr0 + gr) * DD + c2;
            float* crow1 = crow0 + 8 * DD;
            #pragma unroll
            for (int db = 0; db < 8; db++) {
                float2 a0 = *(float2*)(red + ((uint32_t)(gr)     * 64 + db * 8 + c2) * 4);
                float2 a1 = *(float2*)(red + ((uint32_t)(gr + 8) * 64 + db * 8 + c2) * 4);
                *(float2*)(crow0 + db * 8) = make_float2(oacc[db*4+0] + a0.x, oacc[db*4+1] + a0.y);
                *(float2*)(crow1 + db * 8) = make_float2(oacc[db*4+2] + a1.x, oacc[db*4+3] + a1.y);
            }
        }
    }
}

extern "C" void kernel_launch(void* const* d_in, const int* in_sizes, int n_in,
                              void* d_out, int out_size) {
    const float* q  = (const float*)d_in[0];
    const float* k  = (const float*)d_in[1];
    const float* v  = (const float*)d_in[2];
    const float* sc = (const float*)d_in[3];
    float* ctx = (float*)d_out;                          // [16,2048,64]
    float* att = (float*)d_out + (size_t)NB * NN * DD;   // [16,2048,2048]

    conv_kernel<<<dim3(16, NB, 3), 256>>>(q, k, v);

    cudaFuncSetAttribute(attn_kernel, cudaFuncAttributeMaxDynamicSharedMemorySize, SMEM_TOTAL);
    dim3 grid(NN / BM, NB);
    attn_kernel<<<grid, TB, SMEM_TOTAL>>>(sc, ctx, att);
}

// round 12
// speedup vs baseline: 1.6483x; 1.2658x over previous
#include <cuda_runtime.h>
#include <cuda_fp16.h>
#include <cstdint>

static constexpr int NB = 16, NN = 2048, DD = 64;
static constexpr int BM = 128, BN = 128, NKT = NN / BN, TB = 512;

// Pre-converted fp16 (hi only), SW128-swizzled, 128-row blocks, 16KB each:
// g_conv[(t*16 + b)*16 + blk], t: 0=Q,1=K,2=V
__device__ __align__(128) uint8_t g_conv[(size_t)3 * 16 * 16 * 16384];

// SMEM:
//   QH 16K @0
//   ST0=16384: 3-stage ring, stride STG3=32KB: {Kh 16K, Vh 16K}
//     (pass 1 fills only the Kh half of each stage)
//   SM_L row-sum scratch; final O-reduce reuses ring area
static constexpr int SM_QH = 0;
static constexpr int ST0 = 16384, STG3 = 32768;
static constexpr int SM_L = ST0 + 3 * STG3;       // 114688
static constexpr int SMEM_TOTAL = SM_L + 1024;    // 115712

__device__ __forceinline__ uint32_t smem_u32(const void* p) {
    uint32_t a;
    asm("{ .reg .u64 t; cvta.to.shared.u64 t, %1; cvt.u32.u64 %0, t; }" : "=r"(a) : "l"(p));
    return a;
}
__device__ __forceinline__ uint32_t sw128(uint32_t bo) { return bo ^ ((bo >> 3) & 0x70); }
__device__ __forceinline__ float ex2f(float x) {
    float y; asm("ex2.approx.f32 %0, %1;" : "=f"(y) : "f"(x)); return y;
}
__device__ __forceinline__ uint32_t hpack(float a, float b) {
    __half2 h = __floats2half2_rn(a, b);
    return *reinterpret_cast<uint32_t*>(&h);
}

__device__ __forceinline__ void cpa16(uint32_t s, const void* g) {
    asm volatile("cp.async.cg.shared.global [%0], [%1], 16;" :: "r"(s), "l"(g));
}
#define CP_COMMIT() asm volatile("cp.async.commit_group;" ::: "memory")
#define CP_WAIT0()  asm volatile("cp.async.wait_group 0;" ::: "memory")
#define CP_WAIT1()  asm volatile("cp.async.wait_group 1;" ::: "memory")

__device__ __forceinline__ void gcopy(uint32_t sdst, const uint8_t* gsrc,
                                      int bytes, int tid) {
    for (int off = tid * 16; off < bytes; off += TB * 16)
        cpa16(sdst + off, gsrc + off);
}

#define LDSM4(r0,r1,r2,r3,ad) \
    asm volatile("ldmatrix.sync.aligned.m8n8.x4.shared.b16 {%0,%1,%2,%3}, [%4];" \
        : "=r"(r0), "=r"(r1), "=r"(r2), "=r"(r3) : "r"(ad))
#define LDSM4T(r0,r1,r2,r3,ad) \
    asm volatile("ldmatrix.sync.aligned.m8n8.x4.trans.shared.b16 {%0,%1,%2,%3}, [%4];" \
        : "=r"(r0), "=r"(r1), "=r"(r2), "=r"(r3) : "r"(ad))

__device__ __forceinline__ void mma16816(float* c, const uint32_t* a, const uint32_t* b) {
    asm volatile("mma.sync.aligned.m16n8k16.row.col.f32.f16.f16.f32 "
        "{%0,%1,%2,%3}, {%4,%5,%6,%7}, {%8,%9}, {%0,%1,%2,%3};"
        : "+f"(c[0]), "+f"(c[1]), "+f"(c[2]), "+f"(c[3])
        : "r"(a[0]), "r"(a[1]), "r"(a[2]), "r"(a[3]), "r"(b[0]), "r"(b[1]));
}

__device__ __forceinline__ void lda_frag(uint32_t* fr, uint32_t tile, int row0, int kbyte) {
    int lane = threadIdx.x & 31;
    int r = row0 + (lane & 7) + (lane & 8);
    int cb = kbyte + ((lane & 16) ? 16 : 0);
    LDSM4(fr[0], fr[1], fr[2], fr[3], tile + sw128((uint32_t)(r * 128 + cb)));
}
__device__ __forceinline__ void ldb_k(uint32_t* fr, uint32_t tile, int n0, int kbyte) {
    int lane = threadIdx.x & 31;
    int r = n0 + (lane & 7) + ((lane & 16) ? 8 : 0);
    int cb = kbyte + ((lane & 8) ? 16 : 0);
    LDSM4(fr[0], fr[1], fr[2], fr[3], tile + sw128((uint32_t)(r * 128 + cb)));
}
__device__ __forceinline__ void ldb_v(uint32_t* fr, uint32_t tile, int k0, int dbyte) {
    int lane = threadIdx.x & 31;
    int r = k0 + (lane & 7) + (lane & 8);
    int cb = dbyte + ((lane & 16) ? 16 : 0);
    LDSM4T(fr[0], fr[1], fr[2], fr[3], tile + sw128((uint32_t)(r * 128 + cb)));
}

// -------------------------------------------------- pre-convert fp32 -> fp16 (hi only)
__global__ void __launch_bounds__(256)
conv_kernel(const float* __restrict__ q, const float* __restrict__ k,
            const float* __restrict__ v)
{
    const int blk = blockIdx.x, b = blockIdx.y, t = blockIdx.z;
    const float* src = (t == 0 ? q : (t == 1 ? k : v)) + ((size_t)b * NN + blk * 128) * DD;
    uint8_t* dH = g_conv + (((size_t)t * 16 + b) * 16 + blk) * 16384;
    for (int e = threadIdx.x; e < 128 * 16; e += 256) {
        int row = e >> 4, c4 = (e & 15) << 2;
        float4 f = *(const float4*)(src + row * DD + c4);
        uint32_t bo = (uint32_t)(row * 128 + c4 * 2);
        *(uint32_t*)(dH + sw128(bo))     = hpack(f.x, f.y);
        *(uint32_t*)(dH + sw128(bo + 4)) = hpack(f.z, f.w);
    }
}

// -------------------------------------------------- main attention kernel
__global__ void __launch_bounds__(TB, 1)
attn_kernel(const float* __restrict__ scp, float* __restrict__ ctx,
            float* __restrict__ att)
{
    extern __shared__ char smem[];
    const uint32_t sb = smem_u32(smem);
    const int tid = threadIdx.x, lane = tid & 31, wid = tid >> 5;
    const int wr0 = (wid >> 1) * 16;       // warp's first q-row (0..112)
    const int nh = wid & 1;                // n-half (== k-half for PV)
    const int n0 = nh * 64;
    const int gr = lane >> 2, c2 = (lane & 3) * 2;
    const int b = blockIdx.y, q0 = blockIdx.x * BM;
    const float cexp = scp[0] * 1.4426950408889634f;

    const uint8_t* qblk  = g_conv + (((size_t)0 * 16 + b) * 16 + blockIdx.x) * 16384;
    const uint8_t* kbase = g_conv + (((size_t)1 * 16 + b) * 16) * 16384;
    const uint8_t* vbase = g_conv + (((size_t)2 * 16 + b) * 16) * 16384;

    // prologue: group0 = Q panel + Kh(0); group1 = Kh(1)
    gcopy(sb + SM_QH, qblk, 16384, tid);
    gcopy(sb + ST0, kbase, 16384, tid);
    CP_COMMIT();
    gcopy(sb + ST0 + STG3, kbase + 16384, 16384, tid);
    CP_COMMIT();

    float rs0 = 0.f, rs1 = 0.f;
    uint32_t aQ[16];   // Q-hi fragments, persistent across BOTH passes

    // ================= pass 1: row sums (Qh*Kh) =================
    for (int kt = 0; kt < NKT; kt++) {
        if (kt + 1 < NKT) { CP_WAIT1(); } else { CP_WAIT0(); }
        __syncthreads();
        if (kt + 2 < NKT) {
            gcopy(sb + ST0 + (uint32_t)((kt + 2) % 3) * STG3,
                  kbase + (size_t)(kt + 2) * 16384, 16384, tid);
            CP_COMMIT();
        }
        if (kt == 0) {
            #pragma unroll
            for (int ks = 0; ks < 4; ks++)
                lda_frag(aQ + ks * 4, sb + SM_QH, wr0, ks * 32);
        }
        const uint32_t kst = sb + ST0 + (uint32_t)(kt % 3) * STG3;
        float sacc[32];
        #pragma unroll
        for (int i = 0; i < 32; i++) sacc[i] = 0.f;
        #pragma unroll
        for (int ks = 0; ks < 4; ks++) {
            #pragma unroll
            for (int nb2 = 0; nb2 < 4; nb2++) {
                uint32_t bH[4];
                ldb_k(bH, kst, n0 + nb2 * 16, ks * 32);
                float* c0 = sacc + nb2 * 8;
                mma16816(c0, aQ + ks*4, bH);  mma16816(c0 + 4, aQ + ks*4, bH + 2);
            }
        }
        #pragma unroll
        for (int nb = 0; nb < 8; nb++) {
            rs0 += ex2f(sacc[nb*4+0] * cexp) + ex2f(sacc[nb*4+1] * cexp);
            rs1 += ex2f(sacc[nb*4+2] * cexp) + ex2f(sacc[nb*4+3] * cexp);
        }
    }

    // ---- row-sum reduce across the two n-halves ----
    rs0 += __shfl_xor_sync(0xffffffff, rs0, 1);
    rs0 += __shfl_xor_sync(0xffffffff, rs0, 2);
    rs1 += __shfl_xor_sync(0xffffffff, rs1, 1);
    rs1 += __shfl_xor_sync(0xffffffff, rs1, 2);
    float* Ls = (float*)(smem + SM_L);
    __syncthreads();          // all pass-1 stage reads done
    if ((lane & 3) == 0) {
        Ls[nh * 128 + wr0 + gr]     = rs0;
        Ls[nh * 128 + wr0 + 8 + gr] = rs1;
    }
    __syncthreads();
    const float li0 = 1.0f / (Ls[wr0 + gr]     + Ls[128 + wr0 + gr]);
    const float li1 = 1.0f / (Ls[wr0 + 8 + gr] + Ls[128 + wr0 + 8 + gr]);

    float oacc[32];
    #pragma unroll
    for (int i = 0; i < 32; i++) oacc[i] = 0.f;

    // ================= pass 2: attention + O (3-stage ring) =================
    // stage layout: Kh @ +0, Vh @ +16384
    {
        uint32_t s0a = sb + ST0;
        gcopy(s0a,         kbase, 16384, tid);
        gcopy(s0a + 16384, vbase, 16384, tid);
        CP_COMMIT();
        uint32_t s1a = sb + ST0 + STG3;
        gcopy(s1a,         kbase + 16384, 16384, tid);
        gcopy(s1a + 16384, vbase + 16384, 16384, tid);
        CP_COMMIT();
    }

    for (int kt = 0; kt < NKT; kt++) {
        if (kt + 1 < NKT) { CP_WAIT1(); } else { CP_WAIT0(); }
        __syncthreads();
        if (kt + 2 < NKT) {
            uint32_t sa = sb + ST0 + (uint32_t)((kt + 2) % 3) * STG3;
            gcopy(sa,         kbase + (size_t)(kt + 2) * 16384, 16384, tid);
            gcopy(sa + 16384, vbase + (size_t)(kt + 2) * 16384, 16384, tid);
            CP_COMMIT();
        }
        const uint32_t stg = sb + ST0 + (uint32_t)(kt % 3) * STG3;
        const uint32_t vst = stg + 16384;

        // QK: identical 1-product recompute (same aQ, same K bits -> same e as pass 1)
        float sacc[32];
        #pragma unroll
        for (int i = 0; i < 32; i++) sacc[i] = 0.f;
        #pragma unroll
        for (int ks = 0; ks < 4; ks++) {
            #pragma unroll
            for (int nb2 = 0; nb2 < 4; nb2++) {
                uint32_t bH[4];
                ldb_k(bH, stg, n0 + nb2 * 16, ks * 32);
                float* c0 = sacc + nb2 * 8;
                mma16816(c0, aQ + ks*4, bH);  mma16816(c0 + 4, aQ + ks*4, bH + 2);
            }
        }

        // interleaved: per ks -> epilogue(2 nb blocks) then PV(ks)
        float* arow0 = att + ((size_t)b * NN + q0 + wr0 + gr) * NN + kt * BN + n0 + c2;
        float* arow1 = arow0 + (size_t)8 * NN;
        #pragma unroll
        for (int ks = 0; ks < 4; ks++) {
            uint32_t ph[4];
            #pragma unroll
            for (int j = 0; j < 2; j++) {
                const int nb = 2 * ks + j;
                float e0 = ex2f(sacc[nb*4+0] * cexp);
                float e1 = ex2f(sacc[nb*4+1] * cexp);
                float e2 = ex2f(sacc[nb*4+2] * cexp);
                float e3 = ex2f(sacc[nb*4+3] * cexp);
                *(float2*)(arow0 + nb * 8) = make_float2(e0 * li0, e1 * li0);
                *(float2*)(arow1 + nb * 8) = make_float2(e2 * li1, e3 * li1);
                ph[j*2 + 0] = hpack(e0, e1);
                ph[j*2 + 1] = hpack(e2, e3);
            }
            const int k0 = n0 + ks * 16;
            #pragma unroll
            for (int db2 = 0; db2 < 4; db2++) {
                uint32_t bH[4];
                ldb_v(bH, vst, k0, db2 * 32);
                float* c0 = oacc + db2 * 8;
                mma16816(c0, ph, bH);     mma16816(c0 + 4, ph, bH + 2);
            }
        }
    }

    // ---- normalize O, reduce across nh warp-pairs, write context ----
    #pragma unroll
    for (int db = 0; db < 8; db++) {
        oacc[db*4+0] *= li0;  oacc[db*4+1] *= li0;
        oacc[db*4+2] *= li1;  oacc[db*4+3] *= li1;
    }
    __syncthreads();   // all stage reads done; ring area reusable
    {
        char* red = smem + ST0 + (size_t)(wid >> 1) * 4096;
        if (nh == 1) {
            #pragma unroll
            for (int db = 0; db < 8; db++) {
                *(float2*)(red + ((uint32_t)(gr)     * 64 + db * 8 + c2) * 4) =
                    make_float2(oacc[db*4+0], oacc[db*4+1]);
                *(float2*)(red + ((uint32_t)(gr + 8) * 64 + db * 8 + c2) * 4) =
                    make_float2(oacc[db*4+2], oacc[db*4+3]);
            }
        }
        __syncthreads();
        if (nh == 0) {
            float* crow0 = ctx + ((size_t)b * NN + q0 + wr0 + gr) * DD + c2;
            float* crow1 = crow0 + 8 * DD;
            #pragma unroll
            for (int db = 0; db < 8; db++) {
                float2 a0 = *(float2*)(red + ((uint32_t)(gr)     * 64 + db * 8 + c2) * 4);
                float2 a1 = *(float2*)(red + ((uint32_t)(gr + 8) * 64 + db * 8 + c2) * 4);
                *(float2*)(crow0 + db * 8) = make_float2(oacc[db*4+0] + a0.x, oacc[db*4+1] + a0.y);
                *(float2*)(crow1 + db * 8) = make_float2(oacc[db*4+2] + a1.x, oacc[db*4+3] + a1.y);
            }
        }
    }
}

extern "C" void kernel_launch(void* const* d_in, const int* in_sizes, int n_in,
                              void* d_out, int out_size) {
    const float* q  = (const float*)d_in[0];
    const float* k  = (const float*)d_in[1];
    const float* v  = (const float*)d_in[2];
    const float* sc = (const float*)d_in[3];
    float* ctx = (float*)d_out;                          // [16,2048,64]
    float* att = (float*)d_out + (size_t)NB * NN * DD;   // [16,2048,2048]

    conv_kernel<<<dim3(16, NB, 3), 256>>>(q, k, v);

    cudaFuncSetAttribute(attn_kernel, cudaFuncAttributeMaxDynamicSharedMemorySize, SMEM_TOTAL);
    dim3 grid(NN / BM, NB);
    attn_kernel<<<grid, TB, SMEM_TOTAL>>>(sc, ctx, att);
}

// round 13
// speedup vs baseline: 1.6707x; 1.0136x over previous
#include <cuda_runtime.h>
#include <cuda_fp16.h>
#include <cstdint>

static constexpr int NB = 16, NN = 2048, DD = 64;
static constexpr int BM = 64, BN = 64, NKT = NN / BN, TB = 256;

// Pre-converted fp16 (hi only), SW128-swizzled. For each (t,b): 256KB contiguous,
// rows 0..2047, 128B per row (swizzle within the 128B line). t: 0=Q,1=K,2=V
__device__ __align__(128) uint8_t g_conv[(size_t)3 * 16 * 16 * 16384];

// SMEM (57KB/CTA -> 2 CTAs/SM):
//   QH 8K @0 (64 rows x 128B)
//   ST0=8192: 3-stage ring, stride STG3=16KB: {Kh 8K, Vh 8K}
//     (pass 1 fills only the Kh half)
//   SM_L row-sum scratch; final O-reduce reuses ring area
static constexpr int SM_QH = 0;
static constexpr int ST0 = 8192, STG3 = 16384;
static constexpr int SM_L = ST0 + 3 * STG3;       // 57344
static constexpr int SMEM_TOTAL = SM_L + 512;     // 57856

__device__ __forceinline__ uint32_t smem_u32(const void* p) {
    uint32_t a;
    asm("{ .reg .u64 t; cvta.to.shared.u64 t, %1; cvt.u32.u64 %0, t; }" : "=r"(a) : "l"(p));
    return a;
}
__device__ __forceinline__ uint32_t sw128(uint32_t bo) { return bo ^ ((bo >> 3) & 0x70); }
__device__ __forceinline__ float ex2f(float x) {
    float y; asm("ex2.approx.f32 %0, %1;" : "=f"(y) : "f"(x)); return y;
}
__device__ __forceinline__ uint32_t hpack(float a, float b) {
    __half2 h = __floats2half2_rn(a, b);
    return *reinterpret_cast<uint32_t*>(&h);
}

__device__ __forceinline__ void cpa16(uint32_t s, const void* g) {
    asm volatile("cp.async.cg.shared.global [%0], [%1], 16;" :: "r"(s), "l"(g));
}
#define CP_COMMIT() asm volatile("cp.async.commit_group;" ::: "memory")
#define CP_WAIT0()  asm volatile("cp.async.wait_group 0;" ::: "memory")
#define CP_WAIT1()  asm volatile("cp.async.wait_group 1;" ::: "memory")

__device__ __forceinline__ void gcopy(uint32_t sdst, const uint8_t* gsrc,
                                      int bytes, int tid) {
    for (int off = tid * 16; off < bytes; off += TB * 16)
        cpa16(sdst + off, gsrc + off);
}

#define LDSM4(r0,r1,r2,r3,ad) \
    asm volatile("ldmatrix.sync.aligned.m8n8.x4.shared.b16 {%0,%1,%2,%3}, [%4];" \
        : "=r"(r0), "=r"(r1), "=r"(r2), "=r"(r3) : "r"(ad))
#define LDSM4T(r0,r1,r2,r3,ad) \
    asm volatile("ldmatrix.sync.aligned.m8n8.x4.trans.shared.b16 {%0,%1,%2,%3}, [%4];" \
        : "=r"(r0), "=r"(r1), "=r"(r2), "=r"(r3) : "r"(ad))

__device__ __forceinline__ void mma16816(float* c, const uint32_t* a, const uint32_t* b) {
    asm volatile("mma.sync.aligned.m16n8k16.row.col.f32.f16.f16.f32 "
        "{%0,%1,%2,%3}, {%4,%5,%6,%7}, {%8,%9}, {%0,%1,%2,%3};"
        : "+f"(c[0]), "+f"(c[1]), "+f"(c[2]), "+f"(c[3])
        : "r"(a[0]), "r"(a[1]), "r"(a[2]), "r"(a[3]), "r"(b[0]), "r"(b[1]));
}

__device__ __forceinline__ void lda_frag(uint32_t* fr, uint32_t tile, int row0, int kbyte) {
    int lane = threadIdx.x & 31;
    int r = row0 + (lane & 7) + (lane & 8);
    int cb = kbyte + ((lane & 16) ? 16 : 0);
    LDSM4(fr[0], fr[1], fr[2], fr[3], tile + sw128((uint32_t)(r * 128 + cb)));
}
__device__ __forceinline__ void ldb_k(uint32_t* fr, uint32_t tile, int n0, int kbyte) {
    int lane = threadIdx.x & 31;
    int r = n0 + (lane & 7) + ((lane & 16) ? 8 : 0);
    int cb = kbyte + ((lane & 8) ? 16 : 0);
    LDSM4(fr[0], fr[1], fr[2], fr[3], tile + sw128((uint32_t)(r * 128 + cb)));
}
__device__ __forceinline__ void ldb_v(uint32_t* fr, uint32_t tile, int k0, int dbyte) {
    int lane = threadIdx.x & 31;
    int r = k0 + (lane & 7) + (lane & 8);
    int cb = dbyte + ((lane & 16) ? 16 : 0);
    LDSM4T(fr[0], fr[1], fr[2], fr[3], tile + sw128((uint32_t)(r * 128 + cb)));
}

// -------------------------------------------------- pre-convert fp32 -> fp16 (hi only)
__global__ void __launch_bounds__(256)
conv_kernel(const float* __restrict__ q, const float* __restrict__ k,
            const float* __restrict__ v)
{
    const int blk = blockIdx.x, b = blockIdx.y, t = blockIdx.z;
    const float* src = (t == 0 ? q : (t == 1 ? k : v)) + ((size_t)b * NN + blk * 128) * DD;
    uint8_t* dH = g_conv + (((size_t)t * 16 + b) * 16 + blk) * 16384;
    for (int e = threadIdx.x; e < 128 * 16; e += 256) {
        int row = e >> 4, c4 = (e & 15) << 2;
        float4 f = *(const float4*)(src + row * DD + c4);
        uint32_t bo = (uint32_t)(row * 128 + c4 * 2);
        *(uint32_t*)(dH + sw128(bo))     = hpack(f.x, f.y);
        *(uint32_t*)(dH + sw128(bo + 4)) = hpack(f.z, f.w);
    }
}

// -------------------------------------------------- main attention kernel
__global__ void __launch_bounds__(TB, 2)
attn_kernel(const float* __restrict__ scp, float* __restrict__ ctx,
            float* __restrict__ att)
{
    extern __shared__ char smem[];
    const uint32_t sb = smem_u32(smem);
    const int tid = threadIdx.x, lane = tid & 31, wid = tid >> 5;
    const int wr0 = (wid >> 1) * 16;       // warp's first q-row (0..48)
    const int nh = wid & 1;                // n-half (== k-half for PV)
    const int n0 = nh * 32;
    const int gr = lane >> 2, c2 = (lane & 3) * 2;
    const int b = blockIdx.y, q0 = blockIdx.x * BM;
    const float cexp = scp[0] * 1.4426950408889634f;

    // per-(t,b) regions are 256KB contiguous, rows at r*128 bytes
    const uint8_t* qsrc  = g_conv + (((size_t)0 * 16 + b) * 16) * 16384 + (size_t)blockIdx.x * 8192;
    const uint8_t* kbase = g_conv + (((size_t)1 * 16 + b) * 16) * 16384;
    const uint8_t* vbase = g_conv + (((size_t)2 * 16 + b) * 16) * 16384;

    // prologue: group0 = Q panel + Kh(0); group1 = Kh(1)
    gcopy(sb + SM_QH, qsrc, 8192, tid);
    gcopy(sb + ST0, kbase, 8192, tid);
    CP_COMMIT();
    gcopy(sb + ST0 + STG3, kbase + 8192, 8192, tid);
    CP_COMMIT();

    float rs0 = 0.f, rs1 = 0.f;
    uint32_t aQ[16];   // Q fragments, persistent across BOTH passes

    // ================= pass 1: row sums (Qh*Kh, fp16 exp) =================
    for (int kt = 0; kt < NKT; kt++) {
        if (kt + 1 < NKT) { CP_WAIT1(); } else { CP_WAIT0(); }
        __syncthreads();
        if (kt + 2 < NKT) {
            gcopy(sb + ST0 + (uint32_t)((kt + 2) % 3) * STG3,
                  kbase + (size_t)(kt + 2) * 8192, 8192, tid);
            CP_COMMIT();
        }
        if (kt == 0) {
            #pragma unroll
            for (int ks = 0; ks < 4; ks++)
                lda_frag(aQ + ks * 4, sb + SM_QH, wr0, ks * 32);
        }
        const uint32_t kst = sb + ST0 + (uint32_t)(kt % 3) * STG3;
        float sacc[16];
        #pragma unroll
        for (int i = 0; i < 16; i++) sacc[i] = 0.f;
        #pragma unroll
        for (int ks = 0; ks < 4; ks++) {
            #pragma unroll
            for (int nb2 = 0; nb2 < 2; nb2++) {
                uint32_t bH[4];
                ldb_k(bH, kst, n0 + nb2 * 16, ks * 32);
                float* c0 = sacc + nb2 * 8;
                mma16816(c0, aQ + ks*4, bH);  mma16816(c0 + 4, aQ + ks*4, bH + 2);
            }
        }
        #pragma unroll
        for (int nb = 0; nb < 4; nb++) {
            __half2 ha = __floats2half2_rn(sacc[nb*4+0] * cexp, sacc[nb*4+1] * cexp);
            __half2 hb = __floats2half2_rn(sacc[nb*4+2] * cexp, sacc[nb*4+3] * cexp);
            float2 ea = __half22float2(h2exp2(ha));
            float2 eb = __half22float2(h2exp2(hb));
            rs0 += ea.x + ea.y;
            rs1 += eb.x + eb.y;
        }
    }

    // ---- row-sum reduce across the two n-halves ----
    rs0 += __shfl_xor_sync(0xffffffff, rs0, 1);
    rs0 += __shfl_xor_sync(0xffffffff, rs0, 2);
    rs1 += __shfl_xor_sync(0xffffffff, rs1, 1);
    rs1 += __shfl_xor_sync(0xffffffff, rs1, 2);
    float* Ls = (float*)(smem + SM_L);
    __syncthreads();          // all pass-1 stage reads done
    if ((lane & 3) == 0) {
        Ls[nh * 64 + wr0 + gr]     = rs0;
        Ls[nh * 64 + wr0 + 8 + gr] = rs1;
    }
    __syncthreads();
    const float li0 = 1.0f / (Ls[wr0 + gr]     + Ls[64 + wr0 + gr]);
    const float li1 = 1.0f / (Ls[wr0 + 8 + gr] + Ls[64 + wr0 + 8 + gr]);

    float oacc[32];
    #pragma unroll
    for (int i = 0; i < 32; i++) oacc[i] = 0.f;

    // ================= pass 2: attention + O (3-stage ring) =================
    // stage layout: Kh @ +0, Vh @ +8192
    {
        uint32_t s0a = sb + ST0;
        gcopy(s0a,        kbase, 8192, tid);
        gcopy(s0a + 8192, vbase, 8192, tid);
        CP_COMMIT();
        uint32_t s1a = sb + ST0 + STG3;
        gcopy(s1a,        kbase + 8192, 8192, tid);
        gcopy(s1a + 8192, vbase + 8192, 8192, tid);
        CP_COMMIT();
    }

    for (int kt = 0; kt < NKT; kt++) {
        if (kt + 1 < NKT) { CP_WAIT1(); } else { CP_WAIT0(); }
        __syncthreads();
        if (kt + 2 < NKT) {
            uint32_t sa = sb + ST0 + (uint32_t)((kt + 2) % 3) * STG3;
            gcopy(sa,        kbase + (size_t)(kt + 2) * 8192, 8192, tid);
            gcopy(sa + 8192, vbase + (size_t)(kt + 2) * 8192, 8192, tid);
            CP_COMMIT();
        }
        const uint32_t stg = sb + ST0 + (uint32_t)(kt % 3) * STG3;
        const uint32_t vst = stg + 8192;

        // QK: identical 1-product recompute (same aQ, same K bits as pass 1)
        float sacc[16];
        #pragma unroll
        for (int i = 0; i < 16; i++) sacc[i] = 0.f;
        #pragma unroll
        for (int ks = 0; ks < 4; ks++) {
            #pragma unroll
            for (int nb2 = 0; nb2 < 2; nb2++) {
                uint32_t bH[4];
                ldb_k(bH, stg, n0 + nb2 * 16, ks * 32);
                float* c0 = sacc + nb2 * 8;
                mma16816(c0, aQ + ks*4, bH);  mma16816(c0 + 4, aQ + ks*4, bH + 2);
            }
        }

        // interleaved: per ks2 -> epilogue(2 nb blocks) then PV(ks2)
        float* arow0 = att + ((size_t)b * NN + q0 + wr0 + gr) * NN + kt * BN + n0 + c2;
        float* arow1 = arow0 + (size_t)8 * NN;
        #pragma unroll
        for (int ks2 = 0; ks2 < 2; ks2++) {
            uint32_t ph[4];
            #pragma unroll
            for (int j = 0; j < 2; j++) {
                const int nb = 2 * ks2 + j;
                float e0 = ex2f(sacc[nb*4+0] * cexp);
                float e1 = ex2f(sacc[nb*4+1] * cexp);
                float e2 = ex2f(sacc[nb*4+2] * cexp);
                float e3 = ex2f(sacc[nb*4+3] * cexp);
                *(float2*)(arow0 + nb * 8) = make_float2(e0 * li0, e1 * li0);
                *(float2*)(arow1 + nb * 8) = make_float2(e2 * li1, e3 * li1);
                ph[j*2 + 0] = hpack(e0, e1);
                ph[j*2 + 1] = hpack(e2, e3);
            }
            const int k0 = n0 + ks2 * 16;
            #pragma unroll
            for (int db2 = 0; db2 < 4; db2++) {
                uint32_t bH[4];
                ldb_v(bH, vst, k0, db2 * 32);
                float* c0 = oacc + db2 * 8;
                mma16816(c0, ph, bH);     mma16816(c0 + 4, ph, bH + 2);
            }
        }
    }

    // ---- normalize O, reduce across nh warp-pairs, write context ----
    #pragma unroll
    for (int db2 = 0; db2 < 4; db2++) {
        oacc[db2*8+0] *= li0;  oacc[db2*8+1] *= li0;
        oacc[db2*8+2] *= li1;  oacc[db2*8+3] *= li1;
        oacc[db2*8+4] *= li0;  oacc[db2*8+5] *= li0;
        oacc[db2*8+6] *= li1;  oacc[db2*8+7] *= li1;
    }
    __syncthreads();   // all stage reads done; ring area reusable
    {
        char* red = smem + ST0 + (size_t)(wid >> 1) * 4096;  // 16 rows x 64 cols f32
        if (nh == 1) {
            #pragma unroll
            for (int db = 0; db < 8; db++) {
                const int q = (db >> 1) * 8 + (db & 1) * 4;
                *(float2*)(red + ((uint32_t)(gr)     * 64 + db * 8 + c2) * 4) =
                    make_float2(oacc[q+0], oacc[q+1]);
                *(float2*)(red + ((uint32_t)(gr + 8) * 64 + db * 8 + c2) * 4) =
                    make_float2(oacc[q+2], oacc[q+3]);
            }
        }
        __syncthreads();
        if (nh == 0) {
            float* crow0 = ctx + ((size_t)b * NN + q0 + wr0 + gr) * DD + c2;
            float* crow1 = crow0 + 8 * DD;
            #pragma unroll
            for (int db = 0; db < 8; db++) {
                const int q = (db >> 1) * 8 + (db & 1) * 4;
                float2 a0 = *(float2*)(red + ((uint32_t)(gr)     * 64 + db * 8 + c2) * 4);
                float2 a1 = *(float2*)(red + ((uint32_t)(gr + 8) * 64 + db * 8 + c2) * 4);
                *(float2*)(crow0 + db * 8) = make_float2(oacc[q+0] + a0.x, oacc[q+1] + a0.y);
                *(float2*)(crow1 + db * 8) = make_float2(oacc[q+2] + a1.x, oacc[q+3] + a1.y);
            }
        }
    }
}

extern "C" void kernel_launch(void* const* d_in, const int* in_sizes, int n_in,
                              void* d_out, int out_size) {
    const float* q  = (const float*)d_in[0];
    const float* k  = (const float*)d_in[1];
    const float* v  = (const float*)d_in[2];
    const float* sc = (const float*)d_in[3];
    float* ctx = (float*)d_out;                          // [16,2048,64]
    float* att = (float*)d_out + (size_t)NB * NN * DD;   // [16,2048,2048]

    conv_kernel<<<dim3(16, NB, 3), 256>>>(q, k, v);

    cudaFuncSetAttribute(attn_kernel, cudaFuncAttributeMaxDynamicSharedMemorySize, SMEM_TOTAL);
    dim3 grid(NN / BM, NB);
    attn_kernel<<<grid, TB, SMEM_TOTAL>>>(sc, ctx, att);
}